// round 4
// baseline (speedup 1.0000x reference)
#include <cuda_runtime.h>

// BSplineTransformation: x (16,3,1024,1024) f32, control_points (1,2,35,35) f32
// out = concat(transformed (16,3,1024,1024), deformation_field (2,1024,1024))

#define HH 1024
#define WW 1024
#define NPIX (HH*WW)
#define NB 16
#define NC 3
#define CP 35
#define CP2 (CP*CP)
#define BATCHES_PER_BLOCK 4
#define PIX_PER_THREAD 4

__global__ __launch_bounds__(256) void bspline_kernel(
    const float* __restrict__ x,
    const float* __restrict__ cp,
    float* __restrict__ out)
{
    __shared__ float scp[2*CP2];
    for (int t = threadIdx.x; t < 2*CP2; t += 256) scp[t] = cp[t];
    __syncthreads();

    const int p0 = (blockIdx.x * 256 + threadIdx.x) * PIX_PER_THREAD; // 4 consecutive pixels, same row
    const int i  = p0 >> 10;
    const float gy = fmaf((float)i, 2.0f / 1023.0f, -1.0f);

    int   q00[PIX_PER_THREAD], q01[PIX_PER_THREAD], q10[PIX_PER_THREAD], q11[PIX_PER_THREAD];
    float axv[PIX_PER_THREAD], ayv[PIX_PER_THREAD];
    float d0v[PIX_PER_THREAD], d1v[PIX_PER_THREAD];

    #pragma unroll
    for (int k = 0; k < PIX_PER_THREAD; k++) {
        const int p = p0 + k;
        const int j = p & 1023;
        const float gx = fmaf((float)j, 2.0f / 1023.0f, -1.0f);

        // ---- deformation: grid_sample(control_points, border, align_corners) ----
        const float cx = (gx + 1.0f) * 17.0f;
        const float cy = (gy + 1.0f) * 17.0f;
        float icx = fminf(fmaxf((cx + 1.0f) * 17.0f, 0.0f), 34.0f);
        float icy = fminf(fmaxf((cy + 1.0f) * 17.0f, 0.0f), 34.0f);
        const float fcx = floorf(icx);
        const float fcy = floorf(icy);
        const int cx0 = (int)fcx;
        const int cy0 = (int)fcy;
        const int cx1 = min(cx0 + 1, CP - 1);
        const int cy1 = min(cy0 + 1, CP - 1);
        const float wx = icx - fcx;
        const float wy = icy - fcy;

        const int o00 = cy0 * CP + cx0;
        const int o01 = cy0 * CP + cx1;
        const int o10 = cy1 * CP + cx0;
        const int o11 = cy1 * CP + cx1;

        const float t0 = fmaf(wx, scp[o01] - scp[o00], scp[o00]);
        const float b0 = fmaf(wx, scp[o11] - scp[o10], scp[o10]);
        const float d0 = fmaf(wy, b0 - t0, t0);
        const float t1 = fmaf(wx, scp[CP2+o01] - scp[CP2+o00], scp[CP2+o00]);
        const float b1 = fmaf(wx, scp[CP2+o11] - scp[CP2+o10], scp[CP2+o10]);
        const float d1 = fmaf(wy, b1 - t1, t1);
        d0v[k] = d0; d1v[k] = d1;

        // ---- sample coords for main gather ----
        float sx = fminf(fmaxf((gx + d1 + 1.0f) * 511.5f, 0.0f), 1023.0f);
        float sy = fminf(fmaxf((gy + d0 + 1.0f) * 511.5f, 0.0f), 1023.0f);
        const float fsx = floorf(sx);
        const float fsy = floorf(sy);
        const int ix0 = (int)fsx;
        const int iy0 = (int)fsy;
        const int ix1 = min(ix0 + 1, WW - 1);
        const int iy1 = min(iy0 + 1, HH - 1);
        axv[k] = sx - fsx;
        ayv[k] = sy - fsy;
        q00[k] = (iy0 << 10) + ix0;
        q01[k] = (iy0 << 10) + ix1;
        q10[k] = (iy1 << 10) + ix0;
        q11[k] = (iy1 << 10) + ix1;
    }

    // write deformation field once (vectorized)
    if (blockIdx.y == 0) {
        float* def = out + (long long)NB * NC * NPIX;
        *(float4*)(def + p0)        = make_float4(d0v[0], d0v[1], d0v[2], d0v[3]);
        *(float4*)(def + NPIX + p0) = make_float4(d1v[0], d1v[1], d1v[2], d1v[3]);
    }

    // ---- main gathers: 12 images, 16 independent loads per image, float4 store ----
    const int img_start = blockIdx.y * BATCHES_PER_BLOCK * NC;

    #pragma unroll
    for (int m = 0; m < BATCHES_PER_BLOCK * NC; m++) {
        const float* im = x + ((long long)(img_start + m) << 20);
        float v00[PIX_PER_THREAD], v01[PIX_PER_THREAD], v10[PIX_PER_THREAD], v11[PIX_PER_THREAD];
        #pragma unroll
        for (int k = 0; k < PIX_PER_THREAD; k++) {
            v00[k] = __ldg(im + q00[k]);
            v01[k] = __ldg(im + q01[k]);
            v10[k] = __ldg(im + q10[k]);
            v11[k] = __ldg(im + q11[k]);
        }
        float r[PIX_PER_THREAD];
        #pragma unroll
        for (int k = 0; k < PIX_PER_THREAD; k++) {
            const float top = fmaf(axv[k], v01[k] - v00[k], v00[k]);
            const float bot = fmaf(axv[k], v11[k] - v10[k], v10[k]);
            r[k] = fmaf(ayv[k], bot - top, top);
        }
        *(float4*)(out + ((long long)(img_start + m) << 20) + p0) =
            make_float4(r[0], r[1], r[2], r[3]);
    }
}

extern "C" void kernel_launch(void* const* d_in, const int* in_sizes, int n_in,
                              void* d_out, int out_size)
{
    const float* x  = (const float*)d_in[0];
    const float* cp = (const float*)d_in[1];
    float* out = (float*)d_out;

    dim3 grid(NPIX / (256 * PIX_PER_THREAD), NB / BATCHES_PER_BLOCK);
    bspline_kernel<<<grid, 256>>>(x, cp, out);
}

// round 5
// speedup vs baseline: 1.3953x; 1.3953x over previous
#include <cuda_runtime.h>

// BSplineTransformation: x (16,3,1024,1024) f32, control_points (1,2,35,35) f32
// out = concat(transformed (16,3,1024,1024), deformation_field (2,1024,1024))

#define HH 1024
#define WW 1024
#define NPIX (HH*WW)
#define NB 16
#define NC 3
#define CP 35
#define CP2 (CP*CP)
#define BATCHES_PER_BLOCK 4
#define IMG_UNROLL 2

__global__ __launch_bounds__(256) void bspline_kernel(
    const float* __restrict__ x,
    const float* __restrict__ cp,
    float* __restrict__ out)
{
    __shared__ float scp[2*CP2];
    for (int t = threadIdx.x; t < 2*CP2; t += 256) scp[t] = cp[t];
    __syncthreads();

    const int p = blockIdx.x * 256 + threadIdx.x;   // pixel index (1 per thread)
    const int i = p >> 10;
    const int j = p & 1023;

    const float gy = fmaf((float)i, 2.0f / 1023.0f, -1.0f);
    const float gx = fmaf((float)j, 2.0f / 1023.0f, -1.0f);

    // ---- deformation field: grid_sample(control_points, border, align_corners) ----
    const float cx = (gx + 1.0f) * 17.0f;
    const float cy = (gy + 1.0f) * 17.0f;
    float icx = fminf(fmaxf((cx + 1.0f) * 17.0f, 0.0f), 34.0f);
    float icy = fminf(fmaxf((cy + 1.0f) * 17.0f, 0.0f), 34.0f);
    const float fcx = floorf(icx);
    const float fcy = floorf(icy);
    const int cx0 = (int)fcx;
    const int cy0 = (int)fcy;
    const int cx1 = min(cx0 + 1, CP - 1);
    const int cy1 = min(cy0 + 1, CP - 1);
    const float wx = icx - fcx;
    const float wy = icy - fcy;

    const int o00 = cy0 * CP + cx0;
    const int o01 = cy0 * CP + cx1;
    const int o10 = cy1 * CP + cx0;
    const int o11 = cy1 * CP + cx1;

    const float t0 = fmaf(wx, scp[o01] - scp[o00], scp[o00]);
    const float b0 = fmaf(wx, scp[o11] - scp[o10], scp[o10]);
    const float d0 = fmaf(wy, b0 - t0, t0);
    const float t1 = fmaf(wx, scp[CP2+o01] - scp[CP2+o00], scp[CP2+o00]);
    const float b1 = fmaf(wx, scp[CP2+o11] - scp[CP2+o10], scp[CP2+o10]);
    const float d1 = fmaf(wy, b1 - t1, t1);

    // write deformation field once
    if (blockIdx.y == 0) {
        float* def = out + (long long)NB * NC * NPIX;
        def[p]        = d0;
        def[NPIX + p] = d1;
    }

    // ---- main sample coords ----
    float sx = fminf(fmaxf((gx + d1 + 1.0f) * 511.5f, 0.0f), 1023.0f);
    float sy = fminf(fmaxf((gy + d0 + 1.0f) * 511.5f, 0.0f), 1023.0f);
    const float fsx = floorf(sx);
    const float fsy = floorf(sy);
    const int ix0 = (int)fsx;
    const int iy0 = (int)fsy;
    const int ix1 = min(ix0 + 1, WW - 1);
    const int iy1 = min(iy0 + 1, HH - 1);
    const float ax = sx - fsx;
    const float ay = sy - fsy;

    const int q00 = (iy0 << 10) + ix0;
    const int q01 = (iy0 << 10) + ix1;
    const int q10 = (iy1 << 10) + ix0;
    const int q11 = (iy1 << 10) + ix1;

    // ---- 12 images, batched 2-at-a-time: 8 independent gathers in flight ----
    const int img_start = blockIdx.y * BATCHES_PER_BLOCK * NC;

    #pragma unroll
    for (int m = 0; m < BATCHES_PER_BLOCK * NC; m += IMG_UNROLL) {
        float v00[IMG_UNROLL], v01[IMG_UNROLL], v10[IMG_UNROLL], v11[IMG_UNROLL];
        #pragma unroll
        for (int u = 0; u < IMG_UNROLL; u++) {
            const float* im = x + ((long long)(img_start + m + u) << 20);
            v00[u] = __ldg(im + q00);
            v01[u] = __ldg(im + q01);
            v10[u] = __ldg(im + q10);
            v11[u] = __ldg(im + q11);
        }
        #pragma unroll
        for (int u = 0; u < IMG_UNROLL; u++) {
            const float top = fmaf(ax, v01[u] - v00[u], v00[u]);
            const float bot = fmaf(ax, v11[u] - v10[u], v10[u]);
            out[((long long)(img_start + m + u) << 20) + p] = fmaf(ay, bot - top, top);
        }
    }
}

extern "C" void kernel_launch(void* const* d_in, const int* in_sizes, int n_in,
                              void* d_out, int out_size)
{
    const float* x  = (const float*)d_in[0];
    const float* cp = (const float*)d_in[1];
    float* out = (float*)d_out;

    dim3 grid(NPIX / 256, NB / BATCHES_PER_BLOCK);
    bspline_kernel<<<grid, 256>>>(x, cp, out);
}